// round 13
// baseline (speedup 1.0000x reference)
#include <cuda_runtime.h>

#define HH 512
#define WW 512
#define BATCH 2
#define C2 64
#define MH 504
#define N1 168
#define N2 56
#define N3 19
#define N4 7
#define N5 3

typedef unsigned long long ull;

// scratch (device globals: allocation-free per harness rules)
__device__ float g_d1[BATCH*C2*N1*N1];
__device__ float g_d2[BATCH*C2*N2*N2];
__device__ float g_d3[BATCH*C2*N3*N3];
__device__ float g_d4[BATCH*C2*N4*N4];
__device__ float g_d5[BATCH*C2*N5*N5];
__device__ float g_sA[(size_t)BATCH*C2*HH*WW];

// ---- packed f32x2 helpers ------------------------------------------------
__device__ __forceinline__ ull pk(float lo, float hi) {
    ull r; asm("mov.b64 %0, {%1, %2};" : "=l"(r) : "f"(lo), "f"(hi)); return r;
}
__device__ __forceinline__ void upk(ull v, float& lo, float& hi) {
    asm("mov.b64 {%0, %1}, %2;" : "=f"(lo), "=f"(hi) : "l"(v));
}
__device__ __forceinline__ ull fma2(ull a, ull b, ull c) {
    ull d; asm("fma.rn.f32x2 %0, %1, %2, %3;" : "=l"(d) : "l"(a), "l"(b), "l"(c)); return d;
}

// ---------------------------------------------------------------------------
// K1: FUSED ColorDownsample + ModePool2d + conv1 + MaxLeaky + grouped conv2 +
// MinLeaky + downgrade1 + leaky  ->  d1.  (unchanged, passing)
// ---------------------------------------------------------------------------
#define DY 8
__global__ void __launch_bounds__(512) k_md1(const float* __restrict__ x,
                     const float* __restrict__ w1, const float* __restrict__ b1,
                     const float* __restrict__ w2, const float* __restrict__ b2,
                     const float* __restrict__ dk, const float* __restrict__ db) {
    __shared__ unsigned char srow[3][34][64];   // bins
    __shared__ unsigned char mm[3][24][52];     // mode values (255 = pad sentinel)
    __shared__ float sdk[9];
    int t = threadIdx.x;
    int x0 = blockIdx.x * 16;
    int y0 = blockIdx.y * DY;
    int b  = blockIdx.z;
    if (t < 9) sdk[t] = dk[t];

    int rbase = 3 * y0 - 2, cbase = 3 * x0 - 2;
    const float* xb = x + (size_t)b * 3 * HH * WW;
    for (int i = t; i < 3 * 34 * 58; i += 512) {
        int ch = i / (34 * 58); int rr = i - ch * (34 * 58);
        int r = rr / 58, cc = rr - r * 58;
        int gy = rbase + r, gx = cbase + cc;
        unsigned char v = 0;
        if ((unsigned)gy < HH && (unsigned)gx < WW) {
            int bi = (int)rintf(xb[((size_t)ch * HH + gy) * WW + gx] * (255.0f/16.0f));
            v = (unsigned char)(bi < 0 ? 0 : (bi > 16 ? 16 : bi));
        }
        srow[ch][r][cc] = v;
    }
    __syncthreads();

    if (t < 432) {
        int slice = t % 3;
        int colch = t / 3;
        int col = colch % 48;
        int ch  = colch / 48;
        int r0 = slice * 8;
        int gx = 3 * x0 - 1 + col;
        bool xok = (unsigned)gx < MH;

        ull hq0 = 0, hq1 = 0, hq2 = 0;
        auto haddrow = [&](int rr) {
            #pragma unroll
            for (int d = 0; d < 11; d++) {
                int bv = srow[ch][rr][col + d];
                ull one = 1ULL << ((bv & 7) << 3);
                if (bv < 8) hq0 += one;
                else if (bv < 16) hq1 += one;
                else hq2 += 1ULL;
            }
        };
        auto hsubrow = [&](int rr) {
            #pragma unroll
            for (int d = 0; d < 11; d++) {
                int bv = srow[ch][rr][col + d];
                ull one = 1ULL << ((bv & 7) << 3);
                if (bv < 8) hq0 -= one;
                else if (bv < 16) hq1 -= one;
                else hq2 -= 1ULL;
            }
        };
        for (int rr = r0; rr <= r0 + 10; rr++) haddrow(rr);

        for (int k = 0; k < 8; k++) {
            int mr = r0 + k;
            int gy = 3 * y0 - 1 + mr;
            int best = 0, bcnt = (int)(hq0 & 0xFF);
            #pragma unroll
            for (int bb = 1; bb < 8; bb++) {
                int c = (int)((hq0 >> (bb * 8)) & 0xFF);
                if (c > bcnt) { bcnt = c; best = bb; }
            }
            #pragma unroll
            for (int bb = 0; bb < 8; bb++) {
                int c = (int)((hq1 >> (bb * 8)) & 0xFF);
                if (c > bcnt) { bcnt = c; best = bb + 8; }
            }
            { int c = (int)(hq2 & 0xFF); if (c > bcnt) { bcnt = c; best = 16; } }
            mm[ch][mr][col] = (xok && (unsigned)gy < MH) ? (unsigned char)best : 255;
            if (k < 7) { haddrow(mr + 11); hsubrow(mr); }
        }
    }
    __syncthreads();

    int tx = t & 15;
    int cp = t >> 4;
    int xo = x0 + tx;
    if (xo >= N1) return;

    int c0 = 2 * cp, c1 = c0 + 1;
    float w100 = w1[c0*3], w101 = w1[c0*3+1], w102 = w1[c0*3+2], bb10 = b1[c0];
    float w110 = w1[c1*3], w111 = w1[c1*3+1], w112 = w1[c1*3+2], bb11 = b1[c1];
    float w200 = w2[c0*2], w201 = w2[c0*2+1], bb20 = b2[c0];
    float w210 = w2[c1*2], w211 = w2[c1*2+1], bb21 = b2[c1];
    float bias = db[0];

    size_t base = (size_t)b * C2;
    #pragma unroll
    for (int yl = 0; yl < DY; yl++) {
        float acc0 = 0.f, acc1 = 0.f;
        #pragma unroll
        for (int ky = 0; ky < 3; ky++) {
            int mr = 3 * yl + ky;
            #pragma unroll
            for (int kx = 0; kx < 3; kx++) {
                int lx = 3 * tx + kx;
                unsigned char v0 = mm[0][mr][lx];
                if (v0 == 255) continue;
                float f0 = v0 * 0.0625f;
                float f1 = mm[1][mr][lx] * 0.0625f;
                float f2 = mm[2][mr][lx] * 0.0625f;
                float h0 = fmaf(w100, f0, fmaf(w101, f1, fmaf(w102, f2, bb10)));
                h0 = fminf(h0, fmaf(0.01f, h0 - 0.1f, 0.1f));
                float h1 = fmaf(w110, f0, fmaf(w111, f1, fmaf(w112, f2, bb11)));
                h1 = fminf(h1, fmaf(0.01f, h1 - 0.1f, 0.1f));
                float e0 = fmaf(w200, h0, fmaf(w201, h1, bb20));
                e0 = fmaxf(e0, fmaf(0.01f, e0 - 0.1f, 0.1f));
                float e1 = fmaf(w210, h0, fmaf(w211, h1, bb21));
                e1 = fmaxf(e1, fmaf(0.01f, e1 - 0.1f, 0.1f));
                float kkv = sdk[ky * 3 + kx];
                acc0 = fmaf(kkv, e0, acc0);
                acc1 = fmaf(kkv, e1, acc1);
            }
        }
        int yo = y0 + yl;
        float o0 = acc0 + bias; o0 = fmaxf(o0, 0.01f * o0);
        float o1 = acc1 + bias; o1 = fmaxf(o1, 0.01f * o1);
        g_d1[((base + c0) * N1 + yo) * N1 + xo] = o0;
        g_d1[((base + c1) * N1 + yo) * N1 + xo] = o1;
    }
}

// ---------------------------------------------------------------------------
// K3: ALL remaining pyramid levels in ONE kernel (one block per (b,c)).
// ---------------------------------------------------------------------------
__device__ __forceinline__ void pyr_level(const float* ip, float* op,
                                          int Hin, int Hout,
                                          const float* dk, float db0, int t) {
    for (int i = t; i < Hout * Hout; i += 256) {
        int xo = i % Hout, yo = i / Hout;
        float acc = db0;
        #pragma unroll
        for (int ky = 0; ky < 3; ky++) {
            int yi = 3 * yo - 1 + ky;
            if (yi < 0 || yi >= Hin) continue;
            #pragma unroll
            for (int kx = 0; kx < 3; kx++) {
                int xi = 3 * xo - 1 + kx;
                if (xi < 0 || xi >= Hin) continue;
                acc = fmaf(dk[ky * 3 + kx], ip[yi * Hin + xi], acc);
            }
        }
        op[i] = fmaxf(acc, 0.01f * acc);
    }
}

__global__ void __launch_bounds__(256) k_pyr(const float* __restrict__ dk,
                                             const float* __restrict__ db) {
    __shared__ float sdk[9];
    int t = threadIdx.x;
    int bc = blockIdx.x;
    if (t < 9) sdk[t] = dk[t];
    __syncthreads();
    float db0 = db[0];
    pyr_level(g_d1 + (size_t)bc * N1 * N1, g_d2 + (size_t)bc * N2 * N2, N1, N2, sdk, db0, t);
    __syncthreads();
    pyr_level(g_d2 + (size_t)bc * N2 * N2, g_d3 + (size_t)bc * N3 * N3, N2, N3, sdk, db0, t);
    __syncthreads();
    pyr_level(g_d3 + (size_t)bc * N3 * N3, g_d4 + (size_t)bc * N4 * N4, N3, N4, sdk, db0, t);
    __syncthreads();
    pyr_level(g_d4 + (size_t)bc * N4 * N4, g_d5 + (size_t)bc * N5 * N5, N4, N5, sdk, db0, t);
}

// ---------------------------------------------------------------------------
// K4: accumulate (unchanged, passing; near its instruction floor).
// ---------------------------------------------------------------------------
template<int N, int CW>
__device__ __forceinline__ void acc_level(
        const float* __restrict__ dl0, const float* __restrict__ dl1,
        ull (*tmp)[17], const float* sk,
        int x0, int y0, int tx, int t, int zr0,
        ull bias2, ull a2, ull bn2, float* accL, float* accH) {
    constexpr float scale = (float)N / 512.0f;
    constexpr int NCOL = (31 * N + 511) / 512 + 4;

    float fsx0 = fminf(fmaxf((x0 - 1.5f) * scale - 0.5f, 0.f), (float)(N - 1));
    int cx0 = (int)fsx0;

    float Wf[5][CW];
    #pragma unroll
    for (int jr = 0; jr < 5; jr++)
        #pragma unroll
        for (int m = 0; m < CW; m++) Wf[jr][m] = 0.f;
    int m0 = 0;
    #pragma unroll
    for (int j = 0; j < 5; j++) {
        int gx = x0 - 2 + tx + j;
        float fsx = fminf(fmaxf((gx + 0.5f) * scale - 0.5f, 0.f), (float)(N - 1));
        int ix0 = (int)fsx; if (ix0 > N - 1) ix0 = N - 1;
        int ix1 = ix0 + 1 < N ? ix0 + 1 : N - 1;
        float fx = fsx - ix0;
        if (j == 0) m0 = ix0;
        if ((unsigned)gx < WW) {
            int r0 = ix0 - m0, r1 = ix1 - m0;
            float w0 = 1.f - fx, w1 = fx;
            float a[CW];
            #pragma unroll
            for (int mm = 0; mm < CW; mm++) {
                float av = (r0 == mm) ? w0 : 0.f;
                av += (r1 == mm) ? w1 : 0.f;
                a[mm] = av;
            }
            #pragma unroll
            for (int jr = 0; jr < 5; jr++) {
                float kv = sk[jr * 5 + j];
                #pragma unroll
                for (int mm = 0; mm < CW; mm++)
                    Wf[jr][mm] = fmaf(kv, a[mm], Wf[jr][mm]);
            }
        }
    }
    ull W[5][CW];
    #pragma unroll
    for (int jr = 0; jr < 5; jr++)
        #pragma unroll
        for (int mm = 0; mm < CW; mm++)
            W[jr][mm] = pk(Wf[jr][mm], Wf[jr][mm]);
    int mrel = m0 - cx0;

    __syncthreads();
    for (int i = t; i < 36 * NCOL; i += 128) {
        int sy = i / NCOL, j = i - sy * NCOL;
        int gy = y0 - 2 + sy;
        ull val = 0;
        if ((unsigned)gy < HH) {
            float fsy = fminf(fmaxf((gy + 0.5f) * scale - 0.5f, 0.f), (float)(N - 1));
            int iy0 = (int)fsy; if (iy0 > N - 1) iy0 = N - 1;
            int iy1 = iy0 + 1 < N ? iy0 + 1 : N - 1;
            float fy = fsy - iy0;
            int cx = cx0 + j; if (cx > N - 1) cx = N - 1;
            float va0 = dl0[iy0 * N + cx], vb0 = dl0[iy1 * N + cx];
            float va1 = dl1[iy0 * N + cx], vb1 = dl1[iy1 * N + cx];
            val = pk(va0 + fy * (vb0 - va0), va1 + fy * (vb1 - va1));
        }
        tmp[sy][j] = val;
    }
    __syncthreads();
    ull s[8];
    #pragma unroll
    for (int q = 0; q < 8; q++) s[q] = bias2;
    #pragma unroll
    for (int r = 0; r < 12; r++) {
        ull v[CW];
        #pragma unroll
        for (int m = 0; m < CW; m++) v[m] = tmp[zr0 + r][mrel + m];
        #pragma unroll
        for (int jr = 0; jr < 5; jr++) {
            int q = r - jr;
            if (q >= 0 && q < 8) {
                #pragma unroll
                for (int m = 0; m < CW; m++)
                    s[q] = fma2(W[jr][m], v[m], s[q]);
            }
        }
    }
    #pragma unroll
    for (int q = 0; q < 8; q++) {
        ull v = fma2(a2, s[q], bn2);
        float lo, hi; upk(v, lo, hi);
        accL[q] += fmaxf(lo, 0.01f * lo);
        accH[q] += fmaxf(hi, 0.01f * hi);
    }
}

__global__ void __launch_bounds__(128) k_acc(
        const float* __restrict__ ik, const float* __restrict__ ib,
        const float* __restrict__ ig, const float* __restrict__ ibt,
        const float* __restrict__ im, const float* __restrict__ iv) {
    __shared__ ull tmp[36][17];
    __shared__ float sk[25];
    int tx = threadIdx.x, ty = threadIdx.y;
    int t = ty * 32 + tx;
    int x0 = blockIdx.x * 32, y0 = blockIdx.y * 32;
    int cp = blockIdx.z & 31, b = blockIdx.z >> 5;
    int c0 = cp * 2;
    if (t < 25) sk[t] = ik[t];

    float a0 = ig[c0]   * rsqrtf(iv[c0]   + 1e-5f);
    float a1 = ig[c0+1] * rsqrtf(iv[c0+1] + 1e-5f);
    float bc0 = ibt[c0]   - im[c0]   * a0;
    float bc1 = ibt[c0+1] - im[c0+1] * a1;
    ull a2 = pk(a0, a1), bn2 = pk(bc0, bc1);
    float bias = ib[0];
    ull bias2 = pk(bias, bias);

    float accL[8] = {0,0,0,0,0,0,0,0}, accH[8] = {0,0,0,0,0,0,0,0};
    int zr0 = ty * 8;
    __syncthreads();

    size_t cbase = (size_t)b * C2 + c0;
    acc_level<N1,4>(g_d1 + cbase * (N1*N1), g_d1 + (cbase+1) * (N1*N1), tmp, sk,
                    x0, y0, tx, t, zr0, bias2, a2, bn2, accL, accH);
    acc_level<N2,3>(g_d2 + cbase * (N2*N2), g_d2 + (cbase+1) * (N2*N2), tmp, sk,
                    x0, y0, tx, t, zr0, bias2, a2, bn2, accL, accH);
    acc_level<N3,3>(g_d3 + cbase * (N3*N3), g_d3 + (cbase+1) * (N3*N3), tmp, sk,
                    x0, y0, tx, t, zr0, bias2, a2, bn2, accL, accH);
    acc_level<N4,3>(g_d4 + cbase * (N4*N4), g_d4 + (cbase+1) * (N4*N4), tmp, sk,
                    x0, y0, tx, t, zr0, bias2, a2, bn2, accL, accH);
    acc_level<N5,3>(g_d5 + cbase * (N5*N5), g_d5 + (cbase+1) * (N5*N5), tmp, sk,
                    x0, y0, tx, t, zr0, bias2, a2, bn2, accL, accH);

    size_t base0 = ((cbase) * HH + y0 + zr0) * WW + x0 + tx;
    size_t base1 = base0 + (size_t)HH * WW;
    #pragma unroll
    for (int q = 0; q < 8; q++) {
        g_sA[base0 + (size_t)q * WW] = accL[q];
        g_sA[base1 + (size_t)q * WW] = accH[q];
    }
}

// ---------------------------------------------------------------------------
// K5: ALL THREE ft iterations fused in shared memory.
// 128x128 output tile (staged 158x158, halo overhead 1.52x), 512 threads,
// ~207KB dynamic smem (1 block/SM).  16-wide sliding strips; stride 161
// (== 1 mod 32) keeps both passes conflict-free; 2048-float tail pad makes
// strip over-read windows memory-safe.
// ---------------------------------------------------------------------------
#define FTS 158
#define FRS 161
#define FT3_SMEM ((2 * FTS * FRS + 2048) * (int)sizeof(float))
__global__ void __launch_bounds__(512) k_ft3(float* __restrict__ out,
                     const float* __restrict__ fg, const float* __restrict__ fb,
                     const float* __restrict__ fm, const float* __restrict__ fv,
                     const float* __restrict__ fk, const float* __restrict__ fbb,
                     const float* __restrict__ ew) {
    extern __shared__ float sm[];
    float* bufA = sm;                   // [FTS][FRS]
    float* bufB = sm + FTS * FRS;       // [FTS][FRS] (+2048 floats pad after)
    #define BA(r,c) bufA[(r)*FRS + (c)]
    #define BB(r,c) bufB[(r)*FRS + (c)]

    int t = threadIdx.x;
    int x0 = blockIdx.x * 128, y0 = blockIdx.y * 128;
    int c = blockIdx.z & 63, b = blockIdx.z >> 6;

    float k0 = fk[0];
    float gs = fg[c] * rsqrtf(fv[c] + 1e-5f);
    float A  = k0 * gs;
    float Bc = fmaf(k0, fb[c] - fm[c] * gs, fbb[0]);
    float w  = ew[c];

    // stage s = A*score + B (in image), 0 outside — float4 vectorized
    const float* ip = g_sA + ((size_t)b * C2 + c) * HH * WW;
    for (int i = t; i < FTS * 40; i += 512) {
        int r = i / 40, q4 = i - r * 40;
        int gy = y0 - 15 + r;
        int gx0 = x0 - 16 + q4 * 4;           // 16B-aligned when in range
        float4 vv = make_float4(0.f, 0.f, 0.f, 0.f);
        if ((unsigned)gy < HH) {
            if (gx0 >= 0 && gx0 + 3 < WW) {
                vv = *(const float4*)(ip + (size_t)gy * WW + gx0);
                vv.x = fmaf(A, vv.x, Bc); vv.y = fmaf(A, vv.y, Bc);
                vv.z = fmaf(A, vv.z, Bc); vv.w = fmaf(A, vv.w, Bc);
            } else {
                float* pe = &vv.x;
                #pragma unroll
                for (int e = 0; e < 4; e++) {
                    int gx = gx0 + e;
                    if ((unsigned)gx < WW)
                        pe[e] = fmaf(A, ip[(size_t)gy * WW + gx], Bc);
                }
            }
        }
        int cb = q4 * 4 - 1;
        if (cb >= 0) BA(r, cb) = vv.x;
        if (cb + 1 < FTS) BA(r, cb + 1) = vv.y;
        if (cb + 2 < FTS) BA(r, cb + 2) = vv.z;
        if (cb + 3 < FTS) BA(r, cb + 3) = vv.w;
    }

    #pragma unroll
    for (int it = 0; it < 3; it++) {
        const int m = 5 * it;
        const int C = FTS - 10 - 2 * m;         // 148, 138, 128
        const int R = FTS - 2 * m;              // 158, 148, 138
        const int G16 = (C + 15) >> 4;          // 10, 9, 8
        const int lastcol = m + 5 + C - 1;      // = FTS-6-m
        __syncthreads();
        // sliding row sums, 16 cols per task; r-fastest (conflict-free LDS)
        for (int i = t; i < R * G16; i += 512) {
            int g = i / R; int r = m + (i - g * R);
            int xg = m + 5 + g * 16;
            float v[26];
            #pragma unroll
            for (int d = 0; d < 26; d++) v[d] = BA(r, xg - 5 + d);
            float s = v[0];
            #pragma unroll
            for (int d = 1; d < 11; d++) s += v[d];
            BB(r, xg) = s;
            #pragma unroll
            for (int k = 1; k < 16; k++) {
                if (xg + k > lastcol) break;
                s += v[10 + k] - v[k - 1];
                BB(r, xg + k) = s;
            }
        }
        __syncthreads();
        // sliding col sums + emphase + next-iter affine; x-fastest (conflict-free)
        for (int i = t; i < C * G16; i += 512) {
            int g = i / C; int x = m + 5 + (i - g * C);
            int yg = m + 5 + g * 16;
            float cv[26];
            #pragma unroll
            for (int d = 0; d < 26; d++) cv[d] = BB(yg - 5 + d, x);
            float col = cv[0];
            #pragma unroll
            for (int d = 1; d < 11; d++) col += cv[d];
            #pragma unroll
            for (int k = 0; k < 16; k++) {
                int y = yg + k;
                if (y > lastcol) break;
                if (k > 0) col += cv[10 + k] - cv[k - 1];
                int gy = y0 - 15 + y, gx = x0 - 15 + x;
                float o = 0.f;
                if ((unsigned)gy < HH && (unsigned)gx < WW) {
                    float s = BA(y, x);
                    float e = fmaf(w, s - col * (1.0f / 121.0f), s);
                    o = (it < 2) ? fmaf(A, e, Bc) : e;
                }
                BA(y, x) = o;
            }
        }
    }
    __syncthreads();
    float* op = out + ((size_t)b * C2 + c) * HH * WW;
    for (int i = t; i < 128 * 128; i += 512) {
        int ly = i >> 7, lx = i & 127;
        op[(size_t)(y0 + ly) * WW + (x0 + lx)] = BA(15 + ly, 15 + lx);
    }
    #undef BA
    #undef BB
}

// ---------------------------------------------------------------------------
extern "C" void kernel_launch(void* const* d_in, const int* in_sizes, int n_in,
                              void* d_out, int out_size) {
    const float* x        = (const float*)d_in[0];
    const float* w1       = (const float*)d_in[1];
    const float* b1       = (const float*)d_in[2];
    const float* w2       = (const float*)d_in[3];
    const float* b2       = (const float*)d_in[4];
    const float* down_k   = (const float*)d_in[5];
    const float* down_b   = (const float*)d_in[6];
    const float* ft_gamma = (const float*)d_in[7];
    const float* ft_beta  = (const float*)d_in[8];
    const float* ft_mean  = (const float*)d_in[9];
    const float* ft_var   = (const float*)d_in[10];
    const float* ft_k     = (const float*)d_in[11];
    const float* ft_b     = (const float*)d_in[12];
    const float* emph_w   = (const float*)d_in[13];
    const float* interp_k = (const float*)d_in[14];
    const float* interp_b = (const float*)d_in[15];
    const float* i_gamma  = (const float*)d_in[16];
    const float* i_beta   = (const float*)d_in[17];
    const float* i_mean   = (const float*)d_in[18];
    const float* i_var    = (const float*)d_in[19];
    float* out = (float*)d_out;

    static int ft3_attr_set = 0;
    if (!ft3_attr_set) {
        cudaFuncSetAttribute(k_ft3, cudaFuncAttributeMaxDynamicSharedMemorySize, FT3_SMEM);
        ft3_attr_set = 1;
    }

    k_md1<<<dim3(11, 21, 2), 512>>>(x, w1, b1, w2, b2, down_k, down_b);
    k_pyr<<<BATCH * C2, 256>>>(down_k, down_b);
    k_acc<<<dim3(16, 16, 64), dim3(32, 4)>>>(interp_k, interp_b, i_gamma, i_beta, i_mean, i_var);
    k_ft3<<<dim3(4, 4, 128), 512, FT3_SMEM>>>(
        out, ft_gamma, ft_beta, ft_mean, ft_var, ft_k, ft_b, emph_w);
}

// round 14
// speedup vs baseline: 1.0364x; 1.0364x over previous
#include <cuda_runtime.h>

#define HH 512
#define WW 512
#define BATCH 2
#define C2 64
#define MH 504
#define N1 168
#define N2 56
#define N3 19
#define N4 7
#define N5 3

typedef unsigned long long ull;

// scratch (device globals: allocation-free per harness rules)
__device__ float g_d1[BATCH*C2*N1*N1];
__device__ float g_d2[BATCH*C2*N2*N2];
__device__ float g_d3[BATCH*C2*N3*N3];
__device__ float g_d4[BATCH*C2*N4*N4];
__device__ float g_d5[BATCH*C2*N5*N5];
__device__ float g_sA[(size_t)BATCH*C2*HH*WW];

// ---- packed f32x2 helpers ------------------------------------------------
__device__ __forceinline__ ull pk(float lo, float hi) {
    ull r; asm("mov.b64 %0, {%1, %2};" : "=l"(r) : "f"(lo), "f"(hi)); return r;
}
__device__ __forceinline__ void upk(ull v, float& lo, float& hi) {
    asm("mov.b64 {%0, %1}, %2;" : "=f"(lo), "=f"(hi) : "l"(v));
}
__device__ __forceinline__ ull fma2(ull a, ull b, ull c) {
    ull d; asm("fma.rn.f32x2 %0, %1, %2, %3;" : "=l"(d) : "l"(a), "l"(b), "l"(c)); return d;
}

// ---------------------------------------------------------------------------
// K1: FUSED ColorDownsample + ModePool2d + conv1 + MaxLeaky + grouped conv2 +
// MinLeaky + downgrade1 + leaky  ->  d1.  (unchanged, passing)
// ---------------------------------------------------------------------------
#define DY 8
__global__ void __launch_bounds__(512) k_md1(const float* __restrict__ x,
                     const float* __restrict__ w1, const float* __restrict__ b1,
                     const float* __restrict__ w2, const float* __restrict__ b2,
                     const float* __restrict__ dk, const float* __restrict__ db) {
    __shared__ unsigned char srow[3][34][64];   // bins
    __shared__ unsigned char mm[3][24][52];     // mode values (255 = pad sentinel)
    __shared__ float sdk[9];
    int t = threadIdx.x;
    int x0 = blockIdx.x * 16;
    int y0 = blockIdx.y * DY;
    int b  = blockIdx.z;
    if (t < 9) sdk[t] = dk[t];

    int rbase = 3 * y0 - 2, cbase = 3 * x0 - 2;
    const float* xb = x + (size_t)b * 3 * HH * WW;
    for (int i = t; i < 3 * 34 * 58; i += 512) {
        int ch = i / (34 * 58); int rr = i - ch * (34 * 58);
        int r = rr / 58, cc = rr - r * 58;
        int gy = rbase + r, gx = cbase + cc;
        unsigned char v = 0;
        if ((unsigned)gy < HH && (unsigned)gx < WW) {
            int bi = (int)rintf(xb[((size_t)ch * HH + gy) * WW + gx] * (255.0f/16.0f));
            v = (unsigned char)(bi < 0 ? 0 : (bi > 16 ? 16 : bi));
        }
        srow[ch][r][cc] = v;
    }
    __syncthreads();

    if (t < 432) {
        int slice = t % 3;
        int colch = t / 3;
        int col = colch % 48;
        int ch  = colch / 48;
        int r0 = slice * 8;
        int gx = 3 * x0 - 1 + col;
        bool xok = (unsigned)gx < MH;

        ull hq0 = 0, hq1 = 0, hq2 = 0;
        auto haddrow = [&](int rr) {
            #pragma unroll
            for (int d = 0; d < 11; d++) {
                int bv = srow[ch][rr][col + d];
                ull one = 1ULL << ((bv & 7) << 3);
                if (bv < 8) hq0 += one;
                else if (bv < 16) hq1 += one;
                else hq2 += 1ULL;
            }
        };
        auto hsubrow = [&](int rr) {
            #pragma unroll
            for (int d = 0; d < 11; d++) {
                int bv = srow[ch][rr][col + d];
                ull one = 1ULL << ((bv & 7) << 3);
                if (bv < 8) hq0 -= one;
                else if (bv < 16) hq1 -= one;
                else hq2 -= 1ULL;
            }
        };
        for (int rr = r0; rr <= r0 + 10; rr++) haddrow(rr);

        for (int k = 0; k < 8; k++) {
            int mr = r0 + k;
            int gy = 3 * y0 - 1 + mr;
            int best = 0, bcnt = (int)(hq0 & 0xFF);
            #pragma unroll
            for (int bb = 1; bb < 8; bb++) {
                int c = (int)((hq0 >> (bb * 8)) & 0xFF);
                if (c > bcnt) { bcnt = c; best = bb; }
            }
            #pragma unroll
            for (int bb = 0; bb < 8; bb++) {
                int c = (int)((hq1 >> (bb * 8)) & 0xFF);
                if (c > bcnt) { bcnt = c; best = bb + 8; }
            }
            { int c = (int)(hq2 & 0xFF); if (c > bcnt) { bcnt = c; best = 16; } }
            mm[ch][mr][col] = (xok && (unsigned)gy < MH) ? (unsigned char)best : 255;
            if (k < 7) { haddrow(mr + 11); hsubrow(mr); }
        }
    }
    __syncthreads();

    int tx = t & 15;
    int cp = t >> 4;
    int xo = x0 + tx;
    if (xo >= N1) return;

    int c0 = 2 * cp, c1 = c0 + 1;
    float w100 = w1[c0*3], w101 = w1[c0*3+1], w102 = w1[c0*3+2], bb10 = b1[c0];
    float w110 = w1[c1*3], w111 = w1[c1*3+1], w112 = w1[c1*3+2], bb11 = b1[c1];
    float w200 = w2[c0*2], w201 = w2[c0*2+1], bb20 = b2[c0];
    float w210 = w2[c1*2], w211 = w2[c1*2+1], bb21 = b2[c1];
    float bias = db[0];

    size_t base = (size_t)b * C2;
    #pragma unroll
    for (int yl = 0; yl < DY; yl++) {
        float acc0 = 0.f, acc1 = 0.f;
        #pragma unroll
        for (int ky = 0; ky < 3; ky++) {
            int mr = 3 * yl + ky;
            #pragma unroll
            for (int kx = 0; kx < 3; kx++) {
                int lx = 3 * tx + kx;
                unsigned char v0 = mm[0][mr][lx];
                if (v0 == 255) continue;
                float f0 = v0 * 0.0625f;
                float f1 = mm[1][mr][lx] * 0.0625f;
                float f2 = mm[2][mr][lx] * 0.0625f;
                float h0 = fmaf(w100, f0, fmaf(w101, f1, fmaf(w102, f2, bb10)));
                h0 = fminf(h0, fmaf(0.01f, h0 - 0.1f, 0.1f));
                float h1 = fmaf(w110, f0, fmaf(w111, f1, fmaf(w112, f2, bb11)));
                h1 = fminf(h1, fmaf(0.01f, h1 - 0.1f, 0.1f));
                float e0 = fmaf(w200, h0, fmaf(w201, h1, bb20));
                e0 = fmaxf(e0, fmaf(0.01f, e0 - 0.1f, 0.1f));
                float e1 = fmaf(w210, h0, fmaf(w211, h1, bb21));
                e1 = fmaxf(e1, fmaf(0.01f, e1 - 0.1f, 0.1f));
                float kkv = sdk[ky * 3 + kx];
                acc0 = fmaf(kkv, e0, acc0);
                acc1 = fmaf(kkv, e1, acc1);
            }
        }
        int yo = y0 + yl;
        float o0 = acc0 + bias; o0 = fmaxf(o0, 0.01f * o0);
        float o1 = acc1 + bias; o1 = fmaxf(o1, 0.01f * o1);
        g_d1[((base + c0) * N1 + yo) * N1 + xo] = o0;
        g_d1[((base + c1) * N1 + yo) * N1 + xo] = o1;
    }
}

// ---------------------------------------------------------------------------
// K3: ALL remaining pyramid levels in ONE kernel (one block per (b,c)).
// ---------------------------------------------------------------------------
__device__ __forceinline__ void pyr_level(const float* ip, float* op,
                                          int Hin, int Hout,
                                          const float* dk, float db0, int t) {
    for (int i = t; i < Hout * Hout; i += 256) {
        int xo = i % Hout, yo = i / Hout;
        float acc = db0;
        #pragma unroll
        for (int ky = 0; ky < 3; ky++) {
            int yi = 3 * yo - 1 + ky;
            if (yi < 0 || yi >= Hin) continue;
            #pragma unroll
            for (int kx = 0; kx < 3; kx++) {
                int xi = 3 * xo - 1 + kx;
                if (xi < 0 || xi >= Hin) continue;
                acc = fmaf(dk[ky * 3 + kx], ip[yi * Hin + xi], acc);
            }
        }
        op[i] = fmaxf(acc, 0.01f * acc);
    }
}

__global__ void __launch_bounds__(256) k_pyr(const float* __restrict__ dk,
                                             const float* __restrict__ db) {
    __shared__ float sdk[9];
    int t = threadIdx.x;
    int bc = blockIdx.x;
    if (t < 9) sdk[t] = dk[t];
    __syncthreads();
    float db0 = db[0];
    pyr_level(g_d1 + (size_t)bc * N1 * N1, g_d2 + (size_t)bc * N2 * N2, N1, N2, sdk, db0, t);
    __syncthreads();
    pyr_level(g_d2 + (size_t)bc * N2 * N2, g_d3 + (size_t)bc * N3 * N3, N2, N3, sdk, db0, t);
    __syncthreads();
    pyr_level(g_d3 + (size_t)bc * N3 * N3, g_d4 + (size_t)bc * N4 * N4, N3, N4, sdk, db0, t);
    __syncthreads();
    pyr_level(g_d4 + (size_t)bc * N4 * N4, g_d5 + (size_t)bc * N5 * N5, N4, N5, sdk, db0, t);
}

// ---------------------------------------------------------------------------
// K4: accumulate (unchanged, passing; near its instruction floor).
// ---------------------------------------------------------------------------
template<int N, int CW>
__device__ __forceinline__ void acc_level(
        const float* __restrict__ dl0, const float* __restrict__ dl1,
        ull (*tmp)[17], const float* sk,
        int x0, int y0, int tx, int t, int zr0,
        ull bias2, ull a2, ull bn2, float* accL, float* accH) {
    constexpr float scale = (float)N / 512.0f;
    constexpr int NCOL = (31 * N + 511) / 512 + 4;

    float fsx0 = fminf(fmaxf((x0 - 1.5f) * scale - 0.5f, 0.f), (float)(N - 1));
    int cx0 = (int)fsx0;

    float Wf[5][CW];
    #pragma unroll
    for (int jr = 0; jr < 5; jr++)
        #pragma unroll
        for (int m = 0; m < CW; m++) Wf[jr][m] = 0.f;
    int m0 = 0;
    #pragma unroll
    for (int j = 0; j < 5; j++) {
        int gx = x0 - 2 + tx + j;
        float fsx = fminf(fmaxf((gx + 0.5f) * scale - 0.5f, 0.f), (float)(N - 1));
        int ix0 = (int)fsx; if (ix0 > N - 1) ix0 = N - 1;
        int ix1 = ix0 + 1 < N ? ix0 + 1 : N - 1;
        float fx = fsx - ix0;
        if (j == 0) m0 = ix0;
        if ((unsigned)gx < WW) {
            int r0 = ix0 - m0, r1 = ix1 - m0;
            float w0 = 1.f - fx, w1 = fx;
            float a[CW];
            #pragma unroll
            for (int mm = 0; mm < CW; mm++) {
                float av = (r0 == mm) ? w0 : 0.f;
                av += (r1 == mm) ? w1 : 0.f;
                a[mm] = av;
            }
            #pragma unroll
            for (int jr = 0; jr < 5; jr++) {
                float kv = sk[jr * 5 + j];
                #pragma unroll
                for (int mm = 0; mm < CW; mm++)
                    Wf[jr][mm] = fmaf(kv, a[mm], Wf[jr][mm]);
            }
        }
    }
    ull W[5][CW];
    #pragma unroll
    for (int jr = 0; jr < 5; jr++)
        #pragma unroll
        for (int mm = 0; mm < CW; mm++)
            W[jr][mm] = pk(Wf[jr][mm], Wf[jr][mm]);
    int mrel = m0 - cx0;

    __syncthreads();
    for (int i = t; i < 36 * NCOL; i += 128) {
        int sy = i / NCOL, j = i - sy * NCOL;
        int gy = y0 - 2 + sy;
        ull val = 0;
        if ((unsigned)gy < HH) {
            float fsy = fminf(fmaxf((gy + 0.5f) * scale - 0.5f, 0.f), (float)(N - 1));
            int iy0 = (int)fsy; if (iy0 > N - 1) iy0 = N - 1;
            int iy1 = iy0 + 1 < N ? iy0 + 1 : N - 1;
            float fy = fsy - iy0;
            int cx = cx0 + j; if (cx > N - 1) cx = N - 1;
            float va0 = dl0[iy0 * N + cx], vb0 = dl0[iy1 * N + cx];
            float va1 = dl1[iy0 * N + cx], vb1 = dl1[iy1 * N + cx];
            val = pk(va0 + fy * (vb0 - va0), va1 + fy * (vb1 - va1));
        }
        tmp[sy][j] = val;
    }
    __syncthreads();
    ull s[8];
    #pragma unroll
    for (int q = 0; q < 8; q++) s[q] = bias2;
    #pragma unroll
    for (int r = 0; r < 12; r++) {
        ull v[CW];
        #pragma unroll
        for (int m = 0; m < CW; m++) v[m] = tmp[zr0 + r][mrel + m];
        #pragma unroll
        for (int jr = 0; jr < 5; jr++) {
            int q = r - jr;
            if (q >= 0 && q < 8) {
                #pragma unroll
                for (int m = 0; m < CW; m++)
                    s[q] = fma2(W[jr][m], v[m], s[q]);
            }
        }
    }
    #pragma unroll
    for (int q = 0; q < 8; q++) {
        ull v = fma2(a2, s[q], bn2);
        float lo, hi; upk(v, lo, hi);
        accL[q] += fmaxf(lo, 0.01f * lo);
        accH[q] += fmaxf(hi, 0.01f * hi);
    }
}

__global__ void __launch_bounds__(128) k_acc(
        const float* __restrict__ ik, const float* __restrict__ ib,
        const float* __restrict__ ig, const float* __restrict__ ibt,
        const float* __restrict__ im, const float* __restrict__ iv) {
    __shared__ ull tmp[36][17];
    __shared__ float sk[25];
    int tx = threadIdx.x, ty = threadIdx.y;
    int t = ty * 32 + tx;
    int x0 = blockIdx.x * 32, y0 = blockIdx.y * 32;
    int cp = blockIdx.z & 31, b = blockIdx.z >> 5;
    int c0 = cp * 2;
    if (t < 25) sk[t] = ik[t];

    float a0 = ig[c0]   * rsqrtf(iv[c0]   + 1e-5f);
    float a1 = ig[c0+1] * rsqrtf(iv[c0+1] + 1e-5f);
    float bc0 = ibt[c0]   - im[c0]   * a0;
    float bc1 = ibt[c0+1] - im[c0+1] * a1;
    ull a2 = pk(a0, a1), bn2 = pk(bc0, bc1);
    float bias = ib[0];
    ull bias2 = pk(bias, bias);

    float accL[8] = {0,0,0,0,0,0,0,0}, accH[8] = {0,0,0,0,0,0,0,0};
    int zr0 = ty * 8;
    __syncthreads();

    size_t cbase = (size_t)b * C2 + c0;
    acc_level<N1,4>(g_d1 + cbase * (N1*N1), g_d1 + (cbase+1) * (N1*N1), tmp, sk,
                    x0, y0, tx, t, zr0, bias2, a2, bn2, accL, accH);
    acc_level<N2,3>(g_d2 + cbase * (N2*N2), g_d2 + (cbase+1) * (N2*N2), tmp, sk,
                    x0, y0, tx, t, zr0, bias2, a2, bn2, accL, accH);
    acc_level<N3,3>(g_d3 + cbase * (N3*N3), g_d3 + (cbase+1) * (N3*N3), tmp, sk,
                    x0, y0, tx, t, zr0, bias2, a2, bn2, accL, accH);
    acc_level<N4,3>(g_d4 + cbase * (N4*N4), g_d4 + (cbase+1) * (N4*N4), tmp, sk,
                    x0, y0, tx, t, zr0, bias2, a2, bn2, accL, accH);
    acc_level<N5,3>(g_d5 + cbase * (N5*N5), g_d5 + (cbase+1) * (N5*N5), tmp, sk,
                    x0, y0, tx, t, zr0, bias2, a2, bn2, accL, accH);

    size_t base0 = ((cbase) * HH + y0 + zr0) * WW + x0 + tx;
    size_t base1 = base0 + (size_t)HH * WW;
    #pragma unroll
    for (int q = 0; q < 8; q++) {
        g_sA[base0 + (size_t)q * WW] = accL[q];
        g_sA[base1 + (size_t)q * WW] = accH[q];
    }
}

// ---------------------------------------------------------------------------
// K5: ALL THREE ft iterations fused in shared memory.  64x64 tile, 256 thr,
// 3 blocks/SM.  16-wide sliding strips with CLAMPED load windows (values past
// the strip end are unused; clamping keeps reads in-bounds + deterministic).
// Row stride 97 (==1 mod 32): row pass r-fastest, col pass x-fastest.
// ---------------------------------------------------------------------------
#define RS 97
#define FT3_SMEM ((2 * 94 * RS + 512) * (int)sizeof(float))
__global__ void __launch_bounds__(256) k_ft3(float* __restrict__ out,
                     const float* __restrict__ fg, const float* __restrict__ fb,
                     const float* __restrict__ fm, const float* __restrict__ fv,
                     const float* __restrict__ fk, const float* __restrict__ fbb,
                     const float* __restrict__ ew) {
    extern __shared__ float sm[];
    float* bufA = sm;                 // [94][RS]
    float* bufB = sm + 94 * RS;       // [94][RS]
    #define BA(r,c) bufA[(r)*RS + (c)]
    #define BB(r,c) bufB[(r)*RS + (c)]

    int t = threadIdx.x;
    int x0 = blockIdx.x * 64, y0 = blockIdx.y * 64;
    int c = blockIdx.z & 63, b = blockIdx.z >> 6;

    float k0 = fk[0];
    float gs = fg[c] * rsqrtf(fv[c] + 1e-5f);
    float A  = k0 * gs;
    float Bc = fmaf(k0, fb[c] - fm[c] * gs, fbb[0]);
    float w  = ew[c];

    // stage s = A*score + B (in image), 0 outside — float4 vectorized
    const float* ip = g_sA + ((size_t)b * C2 + c) * HH * WW;
    for (int i = t; i < 94 * 24; i += 256) {
        int r = i / 24, q4 = i - r * 24;
        int gy = y0 - 15 + r;
        int gx0 = x0 - 16 + q4 * 4;
        float4 vv = make_float4(0.f, 0.f, 0.f, 0.f);
        if ((unsigned)gy < HH) {
            if (gx0 >= 0 && gx0 + 3 < WW) {
                vv = *(const float4*)(ip + (size_t)gy * WW + gx0);
                vv.x = fmaf(A, vv.x, Bc); vv.y = fmaf(A, vv.y, Bc);
                vv.z = fmaf(A, vv.z, Bc); vv.w = fmaf(A, vv.w, Bc);
            } else {
                float* pe = &vv.x;
                #pragma unroll
                for (int e = 0; e < 4; e++) {
                    int gx = gx0 + e;
                    if ((unsigned)gx < WW)
                        pe[e] = fmaf(A, ip[(size_t)gy * WW + gx], Bc);
                }
            }
        }
        int cb = q4 * 4 - 1;
        if (cb >= 0) BA(r, cb) = vv.x;
        BA(r, cb + 1) = vv.y;
        BA(r, cb + 2) = vv.z;
        BA(r, cb + 3) = vv.w;
    }

    #pragma unroll
    for (int it = 0; it < 3; it++) {
        const int m = 5 * it;
        const int C = 84 - 2 * m;
        const int R = 94 - 2 * m;
        const int G16 = (C + 15) >> 4;          // 6, 5, 5
        const int lastcol = m + 5 + C - 1;
        __syncthreads();
        // sliding row sums, 16 cols per task; r-fastest (conflict-free LDS)
        for (int i = t; i < R * G16; i += 256) {
            int g = i / R; int r = m + (i - g * R);
            int xg = m + 5 + g * 16;
            float v[26];
            #pragma unroll
            for (int d = 0; d < 26; d++) {
                int idx = xg - 5 + d; if (idx > 93) idx = 93;   // clamp (unused tail)
                v[d] = BA(r, idx);
            }
            float s = v[0];
            #pragma unroll
            for (int d = 1; d < 11; d++) s += v[d];
            BB(r, xg) = s;
            #pragma unroll
            for (int k = 1; k < 16; k++) {
                if (xg + k > lastcol) break;
                s += v[10 + k] - v[k - 1];
                BB(r, xg + k) = s;
            }
        }
        __syncthreads();
        // sliding col sums + emphase + next-iter affine; x-fastest (conflict-free)
        for (int i = t; i < C * G16; i += 256) {
            int g = i / C; int x = m + 5 + (i - g * C);
            int yg = m + 5 + g * 16;
            float cv[26];
            #pragma unroll
            for (int d = 0; d < 26; d++) {
                int idx = yg - 5 + d; if (idx > 93) idx = 93;   // clamp (unused tail)
                cv[d] = BB(idx, x);
            }
            float col = cv[0];
            #pragma unroll
            for (int d = 1; d < 11; d++) col += cv[d];
            #pragma unroll
            for (int k = 0; k < 16; k++) {
                int y = yg + k;
                if (y > lastcol) break;
                if (k > 0) col += cv[10 + k] - cv[k - 1];
                int gy = y0 - 15 + y, gx = x0 - 15 + x;
                float o = 0.f;
                if ((unsigned)gy < HH && (unsigned)gx < WW) {
                    float s = BA(y, x);
                    float e = fmaf(w, s - col * (1.0f / 121.0f), s);
                    o = (it < 2) ? fmaf(A, e, Bc) : e;
                }
                BA(y, x) = o;
            }
        }
    }
    __syncthreads();
    float* op = out + ((size_t)b * C2 + c) * HH * WW;
    for (int i = t; i < 64 * 64; i += 256) {
        int ly = i >> 6, lx = i & 63;
        op[(size_t)(y0 + ly) * WW + (x0 + lx)] = BA(15 + ly, 15 + lx);
    }
    #undef BA
    #undef BB
}

// ---------------------------------------------------------------------------
extern "C" void kernel_launch(void* const* d_in, const int* in_sizes, int n_in,
                              void* d_out, int out_size) {
    const float* x        = (const float*)d_in[0];
    const float* w1       = (const float*)d_in[1];
    const float* b1       = (const float*)d_in[2];
    const float* w2       = (const float*)d_in[3];
    const float* b2       = (const float*)d_in[4];
    const float* down_k   = (const float*)d_in[5];
    const float* down_b   = (const float*)d_in[6];
    const float* ft_gamma = (const float*)d_in[7];
    const float* ft_beta  = (const float*)d_in[8];
    const float* ft_mean  = (const float*)d_in[9];
    const float* ft_var   = (const float*)d_in[10];
    const float* ft_k     = (const float*)d_in[11];
    const float* ft_b     = (const float*)d_in[12];
    const float* emph_w   = (const float*)d_in[13];
    const float* interp_k = (const float*)d_in[14];
    const float* interp_b = (const float*)d_in[15];
    const float* i_gamma  = (const float*)d_in[16];
    const float* i_beta   = (const float*)d_in[17];
    const float* i_mean   = (const float*)d_in[18];
    const float* i_var    = (const float*)d_in[19];
    float* out = (float*)d_out;

    static int ft3_attr_set = 0;
    if (!ft3_attr_set) {
        cudaFuncSetAttribute(k_ft3, cudaFuncAttributeMaxDynamicSharedMemorySize, FT3_SMEM);
        ft3_attr_set = 1;
    }

    k_md1<<<dim3(11, 21, 2), 512>>>(x, w1, b1, w2, b2, down_k, down_b);
    k_pyr<<<BATCH * C2, 256>>>(down_k, down_b);
    k_acc<<<dim3(16, 16, 64), dim3(32, 4)>>>(interp_k, interp_b, i_gamma, i_beta, i_mean, i_var);
    k_ft3<<<dim3(8, 8, 128), 256, FT3_SMEM>>>(
        out, ft_gamma, ft_beta, ft_mean, ft_var, ft_k, ft_b, emph_w);
}

// round 15
// speedup vs baseline: 1.0475x; 1.0108x over previous
#include <cuda_runtime.h>

#define HH 512
#define WW 512
#define BATCH 2
#define C2 64
#define MH 504
#define N1 168
#define N2 56
#define N3 19
#define N4 7
#define N5 3

typedef unsigned long long ull;

// scratch (device globals: allocation-free per harness rules)
__device__ float g_d1[BATCH*C2*N1*N1];
__device__ float g_d2[BATCH*C2*N2*N2];
__device__ float g_d3[BATCH*C2*N3*N3];
__device__ float g_d4[BATCH*C2*N4*N4];
__device__ float g_d5[BATCH*C2*N5*N5];
__device__ float g_sA[(size_t)BATCH*C2*HH*WW];

// ---- packed f32x2 helpers ------------------------------------------------
__device__ __forceinline__ ull pk(float lo, float hi) {
    ull r; asm("mov.b64 %0, {%1, %2};" : "=l"(r) : "f"(lo), "f"(hi)); return r;
}
__device__ __forceinline__ void upk(ull v, float& lo, float& hi) {
    asm("mov.b64 {%0, %1}, %2;" : "=f"(lo), "=f"(hi) : "l"(v));
}
__device__ __forceinline__ ull fma2(ull a, ull b, ull c) {
    ull d; asm("fma.rn.f32x2 %0, %1, %2, %3;" : "=l"(d) : "l"(a), "l"(b), "l"(c)); return d;
}

// ---------------------------------------------------------------------------
// K1: FUSED ColorDownsample + ModePool2d + conv1 + MaxLeaky + grouped conv2 +
// MinLeaky + downgrade1 + leaky  ->  d1.  (unchanged, passing)
// ---------------------------------------------------------------------------
#define DY 8
__global__ void __launch_bounds__(512) k_md1(const float* __restrict__ x,
                     const float* __restrict__ w1, const float* __restrict__ b1,
                     const float* __restrict__ w2, const float* __restrict__ b2,
                     const float* __restrict__ dk, const float* __restrict__ db) {
    __shared__ unsigned char srow[3][34][64];   // bins
    __shared__ unsigned char mm[3][24][52];     // mode values (255 = pad sentinel)
    __shared__ float sdk[9];
    int t = threadIdx.x;
    int x0 = blockIdx.x * 16;
    int y0 = blockIdx.y * DY;
    int b  = blockIdx.z;
    if (t < 9) sdk[t] = dk[t];

    int rbase = 3 * y0 - 2, cbase = 3 * x0 - 2;
    const float* xb = x + (size_t)b * 3 * HH * WW;
    for (int i = t; i < 3 * 34 * 58; i += 512) {
        int ch = i / (34 * 58); int rr = i - ch * (34 * 58);
        int r = rr / 58, cc = rr - r * 58;
        int gy = rbase + r, gx = cbase + cc;
        unsigned char v = 0;
        if ((unsigned)gy < HH && (unsigned)gx < WW) {
            int bi = (int)rintf(xb[((size_t)ch * HH + gy) * WW + gx] * (255.0f/16.0f));
            v = (unsigned char)(bi < 0 ? 0 : (bi > 16 ? 16 : bi));
        }
        srow[ch][r][cc] = v;
    }
    __syncthreads();

    if (t < 432) {
        int slice = t % 3;
        int colch = t / 3;
        int col = colch % 48;
        int ch  = colch / 48;
        int r0 = slice * 8;
        int gx = 3 * x0 - 1 + col;
        bool xok = (unsigned)gx < MH;

        ull hq0 = 0, hq1 = 0, hq2 = 0;
        auto haddrow = [&](int rr) {
            #pragma unroll
            for (int d = 0; d < 11; d++) {
                int bv = srow[ch][rr][col + d];
                ull one = 1ULL << ((bv & 7) << 3);
                if (bv < 8) hq0 += one;
                else if (bv < 16) hq1 += one;
                else hq2 += 1ULL;
            }
        };
        auto hsubrow = [&](int rr) {
            #pragma unroll
            for (int d = 0; d < 11; d++) {
                int bv = srow[ch][rr][col + d];
                ull one = 1ULL << ((bv & 7) << 3);
                if (bv < 8) hq0 -= one;
                else if (bv < 16) hq1 -= one;
                else hq2 -= 1ULL;
            }
        };
        for (int rr = r0; rr <= r0 + 10; rr++) haddrow(rr);

        for (int k = 0; k < 8; k++) {
            int mr = r0 + k;
            int gy = 3 * y0 - 1 + mr;
            int best = 0, bcnt = (int)(hq0 & 0xFF);
            #pragma unroll
            for (int bb = 1; bb < 8; bb++) {
                int c = (int)((hq0 >> (bb * 8)) & 0xFF);
                if (c > bcnt) { bcnt = c; best = bb; }
            }
            #pragma unroll
            for (int bb = 0; bb < 8; bb++) {
                int c = (int)((hq1 >> (bb * 8)) & 0xFF);
                if (c > bcnt) { bcnt = c; best = bb + 8; }
            }
            { int c = (int)(hq2 & 0xFF); if (c > bcnt) { bcnt = c; best = 16; } }
            mm[ch][mr][col] = (xok && (unsigned)gy < MH) ? (unsigned char)best : 255;
            if (k < 7) { haddrow(mr + 11); hsubrow(mr); }
        }
    }
    __syncthreads();

    int tx = t & 15;
    int cp = t >> 4;
    int xo = x0 + tx;
    if (xo >= N1) return;

    int c0 = 2 * cp, c1 = c0 + 1;
    float w100 = w1[c0*3], w101 = w1[c0*3+1], w102 = w1[c0*3+2], bb10 = b1[c0];
    float w110 = w1[c1*3], w111 = w1[c1*3+1], w112 = w1[c1*3+2], bb11 = b1[c1];
    float w200 = w2[c0*2], w201 = w2[c0*2+1], bb20 = b2[c0];
    float w210 = w2[c1*2], w211 = w2[c1*2+1], bb21 = b2[c1];
    float bias = db[0];

    size_t base = (size_t)b * C2;
    #pragma unroll
    for (int yl = 0; yl < DY; yl++) {
        float acc0 = 0.f, acc1 = 0.f;
        #pragma unroll
        for (int ky = 0; ky < 3; ky++) {
            int mr = 3 * yl + ky;
            #pragma unroll
            for (int kx = 0; kx < 3; kx++) {
                int lx = 3 * tx + kx;
                unsigned char v0 = mm[0][mr][lx];
                if (v0 == 255) continue;
                float f0 = v0 * 0.0625f;
                float f1 = mm[1][mr][lx] * 0.0625f;
                float f2 = mm[2][mr][lx] * 0.0625f;
                float h0 = fmaf(w100, f0, fmaf(w101, f1, fmaf(w102, f2, bb10)));
                h0 = fminf(h0, fmaf(0.01f, h0 - 0.1f, 0.1f));
                float h1 = fmaf(w110, f0, fmaf(w111, f1, fmaf(w112, f2, bb11)));
                h1 = fminf(h1, fmaf(0.01f, h1 - 0.1f, 0.1f));
                float e0 = fmaf(w200, h0, fmaf(w201, h1, bb20));
                e0 = fmaxf(e0, fmaf(0.01f, e0 - 0.1f, 0.1f));
                float e1 = fmaf(w210, h0, fmaf(w211, h1, bb21));
                e1 = fmaxf(e1, fmaf(0.01f, e1 - 0.1f, 0.1f));
                float kkv = sdk[ky * 3 + kx];
                acc0 = fmaf(kkv, e0, acc0);
                acc1 = fmaf(kkv, e1, acc1);
            }
        }
        int yo = y0 + yl;
        float o0 = acc0 + bias; o0 = fmaxf(o0, 0.01f * o0);
        float o1 = acc1 + bias; o1 = fmaxf(o1, 0.01f * o1);
        g_d1[((base + c0) * N1 + yo) * N1 + xo] = o0;
        g_d1[((base + c1) * N1 + yo) * N1 + xo] = o1;
    }
}

// ---------------------------------------------------------------------------
// K3: ALL remaining pyramid levels in ONE kernel (one block per (b,c)).
// ---------------------------------------------------------------------------
__device__ __forceinline__ void pyr_level(const float* ip, float* op,
                                          int Hin, int Hout,
                                          const float* dk, float db0, int t) {
    for (int i = t; i < Hout * Hout; i += 256) {
        int xo = i % Hout, yo = i / Hout;
        float acc = db0;
        #pragma unroll
        for (int ky = 0; ky < 3; ky++) {
            int yi = 3 * yo - 1 + ky;
            if (yi < 0 || yi >= Hin) continue;
            #pragma unroll
            for (int kx = 0; kx < 3; kx++) {
                int xi = 3 * xo - 1 + kx;
                if (xi < 0 || xi >= Hin) continue;
                acc = fmaf(dk[ky * 3 + kx], ip[yi * Hin + xi], acc);
            }
        }
        op[i] = fmaxf(acc, 0.01f * acc);
    }
}

__global__ void __launch_bounds__(256) k_pyr(const float* __restrict__ dk,
                                             const float* __restrict__ db) {
    __shared__ float sdk[9];
    int t = threadIdx.x;
    int bc = blockIdx.x;
    if (t < 9) sdk[t] = dk[t];
    __syncthreads();
    float db0 = db[0];
    pyr_level(g_d1 + (size_t)bc * N1 * N1, g_d2 + (size_t)bc * N2 * N2, N1, N2, sdk, db0, t);
    __syncthreads();
    pyr_level(g_d2 + (size_t)bc * N2 * N2, g_d3 + (size_t)bc * N3 * N3, N2, N3, sdk, db0, t);
    __syncthreads();
    pyr_level(g_d3 + (size_t)bc * N3 * N3, g_d4 + (size_t)bc * N4 * N4, N3, N4, sdk, db0, t);
    __syncthreads();
    pyr_level(g_d4 + (size_t)bc * N4 * N4, g_d5 + (size_t)bc * N5 * N5, N4, N5, sdk, db0, t);
}

// ---------------------------------------------------------------------------
// K4: accumulate (unchanged, passing; near its instruction floor).
// ---------------------------------------------------------------------------
template<int N, int CW>
__device__ __forceinline__ void acc_level(
        const float* __restrict__ dl0, const float* __restrict__ dl1,
        ull (*tmp)[17], const float* sk,
        int x0, int y0, int tx, int t, int zr0,
        ull bias2, ull a2, ull bn2, float* accL, float* accH) {
    constexpr float scale = (float)N / 512.0f;
    constexpr int NCOL = (31 * N + 511) / 512 + 4;

    float fsx0 = fminf(fmaxf((x0 - 1.5f) * scale - 0.5f, 0.f), (float)(N - 1));
    int cx0 = (int)fsx0;

    float Wf[5][CW];
    #pragma unroll
    for (int jr = 0; jr < 5; jr++)
        #pragma unroll
        for (int m = 0; m < CW; m++) Wf[jr][m] = 0.f;
    int m0 = 0;
    #pragma unroll
    for (int j = 0; j < 5; j++) {
        int gx = x0 - 2 + tx + j;
        float fsx = fminf(fmaxf((gx + 0.5f) * scale - 0.5f, 0.f), (float)(N - 1));
        int ix0 = (int)fsx; if (ix0 > N - 1) ix0 = N - 1;
        int ix1 = ix0 + 1 < N ? ix0 + 1 : N - 1;
        float fx = fsx - ix0;
        if (j == 0) m0 = ix0;
        if ((unsigned)gx < WW) {
            int r0 = ix0 - m0, r1 = ix1 - m0;
            float w0 = 1.f - fx, w1 = fx;
            float a[CW];
            #pragma unroll
            for (int mm = 0; mm < CW; mm++) {
                float av = (r0 == mm) ? w0 : 0.f;
                av += (r1 == mm) ? w1 : 0.f;
                a[mm] = av;
            }
            #pragma unroll
            for (int jr = 0; jr < 5; jr++) {
                float kv = sk[jr * 5 + j];
                #pragma unroll
                for (int mm = 0; mm < CW; mm++)
                    Wf[jr][mm] = fmaf(kv, a[mm], Wf[jr][mm]);
            }
        }
    }
    ull W[5][CW];
    #pragma unroll
    for (int jr = 0; jr < 5; jr++)
        #pragma unroll
        for (int mm = 0; mm < CW; mm++)
            W[jr][mm] = pk(Wf[jr][mm], Wf[jr][mm]);
    int mrel = m0 - cx0;

    __syncthreads();
    for (int i = t; i < 36 * NCOL; i += 128) {
        int sy = i / NCOL, j = i - sy * NCOL;
        int gy = y0 - 2 + sy;
        ull val = 0;
        if ((unsigned)gy < HH) {
            float fsy = fminf(fmaxf((gy + 0.5f) * scale - 0.5f, 0.f), (float)(N - 1));
            int iy0 = (int)fsy; if (iy0 > N - 1) iy0 = N - 1;
            int iy1 = iy0 + 1 < N ? iy0 + 1 : N - 1;
            float fy = fsy - iy0;
            int cx = cx0 + j; if (cx > N - 1) cx = N - 1;
            float va0 = dl0[iy0 * N + cx], vb0 = dl0[iy1 * N + cx];
            float va1 = dl1[iy0 * N + cx], vb1 = dl1[iy1 * N + cx];
            val = pk(va0 + fy * (vb0 - va0), va1 + fy * (vb1 - va1));
        }
        tmp[sy][j] = val;
    }
    __syncthreads();
    ull s[8];
    #pragma unroll
    for (int q = 0; q < 8; q++) s[q] = bias2;
    #pragma unroll
    for (int r = 0; r < 12; r++) {
        ull v[CW];
        #pragma unroll
        for (int m = 0; m < CW; m++) v[m] = tmp[zr0 + r][mrel + m];
        #pragma unroll
        for (int jr = 0; jr < 5; jr++) {
            int q = r - jr;
            if (q >= 0 && q < 8) {
                #pragma unroll
                for (int m = 0; m < CW; m++)
                    s[q] = fma2(W[jr][m], v[m], s[q]);
            }
        }
    }
    #pragma unroll
    for (int q = 0; q < 8; q++) {
        ull v = fma2(a2, s[q], bn2);
        float lo, hi; upk(v, lo, hi);
        accL[q] += fmaxf(lo, 0.01f * lo);
        accH[q] += fmaxf(hi, 0.01f * hi);
    }
}

__global__ void __launch_bounds__(128) k_acc(
        const float* __restrict__ ik, const float* __restrict__ ib,
        const float* __restrict__ ig, const float* __restrict__ ibt,
        const float* __restrict__ im, const float* __restrict__ iv) {
    __shared__ ull tmp[36][17];
    __shared__ float sk[25];
    int tx = threadIdx.x, ty = threadIdx.y;
    int t = ty * 32 + tx;
    int x0 = blockIdx.x * 32, y0 = blockIdx.y * 32;
    int cp = blockIdx.z & 31, b = blockIdx.z >> 5;
    int c0 = cp * 2;
    if (t < 25) sk[t] = ik[t];

    float a0 = ig[c0]   * rsqrtf(iv[c0]   + 1e-5f);
    float a1 = ig[c0+1] * rsqrtf(iv[c0+1] + 1e-5f);
    float bc0 = ibt[c0]   - im[c0]   * a0;
    float bc1 = ibt[c0+1] - im[c0+1] * a1;
    ull a2 = pk(a0, a1), bn2 = pk(bc0, bc1);
    float bias = ib[0];
    ull bias2 = pk(bias, bias);

    float accL[8] = {0,0,0,0,0,0,0,0}, accH[8] = {0,0,0,0,0,0,0,0};
    int zr0 = ty * 8;
    __syncthreads();

    size_t cbase = (size_t)b * C2 + c0;
    acc_level<N1,4>(g_d1 + cbase * (N1*N1), g_d1 + (cbase+1) * (N1*N1), tmp, sk,
                    x0, y0, tx, t, zr0, bias2, a2, bn2, accL, accH);
    acc_level<N2,3>(g_d2 + cbase * (N2*N2), g_d2 + (cbase+1) * (N2*N2), tmp, sk,
                    x0, y0, tx, t, zr0, bias2, a2, bn2, accL, accH);
    acc_level<N3,3>(g_d3 + cbase * (N3*N3), g_d3 + (cbase+1) * (N3*N3), tmp, sk,
                    x0, y0, tx, t, zr0, bias2, a2, bn2, accL, accH);
    acc_level<N4,3>(g_d4 + cbase * (N4*N4), g_d4 + (cbase+1) * (N4*N4), tmp, sk,
                    x0, y0, tx, t, zr0, bias2, a2, bn2, accL, accH);
    acc_level<N5,3>(g_d5 + cbase * (N5*N5), g_d5 + (cbase+1) * (N5*N5), tmp, sk,
                    x0, y0, tx, t, zr0, bias2, a2, bn2, accL, accH);

    size_t base0 = ((cbase) * HH + y0 + zr0) * WW + x0 + tx;
    size_t base1 = base0 + (size_t)HH * WW;
    #pragma unroll
    for (int q = 0; q < 8; q++) {
        g_sA[base0 + (size_t)q * WW] = accL[q];
        g_sA[base1 + (size_t)q * WW] = accH[q];
    }
}

// ---------------------------------------------------------------------------
// K5: ALL THREE ft iterations fused in shared memory.  64x64 tile, 256 thr,
// 3 blocks/SM.  16-wide sliding strips; FULL strips take a clamp-free,
// break-free fast path (window max read provably <= 93); only the tail
// strip (<=1 per row/col, none in iter 3) uses the clamped path.
// Row stride 97 (==1 mod 32): row pass r-fastest, col pass x-fastest.
// ---------------------------------------------------------------------------
#define RS 97
#define FT3_SMEM ((2 * 94 * RS + 512) * (int)sizeof(float))
__global__ void __launch_bounds__(256) k_ft3(float* __restrict__ out,
                     const float* __restrict__ fg, const float* __restrict__ fb,
                     const float* __restrict__ fm, const float* __restrict__ fv,
                     const float* __restrict__ fk, const float* __restrict__ fbb,
                     const float* __restrict__ ew) {
    extern __shared__ float sm[];
    float* bufA = sm;                 // [94][RS]
    float* bufB = sm + 94 * RS;       // [94][RS]
    #define BA(r,c) bufA[(r)*RS + (c)]
    #define BB(r,c) bufB[(r)*RS + (c)]

    int t = threadIdx.x;
    int x0 = blockIdx.x * 64, y0 = blockIdx.y * 64;
    int c = blockIdx.z & 63, b = blockIdx.z >> 6;

    float k0 = fk[0];
    float gs = fg[c] * rsqrtf(fv[c] + 1e-5f);
    float A  = k0 * gs;
    float Bc = fmaf(k0, fb[c] - fm[c] * gs, fbb[0]);
    float w  = ew[c];

    // stage s = A*score + B (in image), 0 outside — float4 vectorized
    const float* ip = g_sA + ((size_t)b * C2 + c) * HH * WW;
    for (int i = t; i < 94 * 24; i += 256) {
        int r = i / 24, q4 = i - r * 24;
        int gy = y0 - 15 + r;
        int gx0 = x0 - 16 + q4 * 4;
        float4 vv = make_float4(0.f, 0.f, 0.f, 0.f);
        if ((unsigned)gy < HH) {
            if (gx0 >= 0 && gx0 + 3 < WW) {
                vv = *(const float4*)(ip + (size_t)gy * WW + gx0);
                vv.x = fmaf(A, vv.x, Bc); vv.y = fmaf(A, vv.y, Bc);
                vv.z = fmaf(A, vv.z, Bc); vv.w = fmaf(A, vv.w, Bc);
            } else {
                float* pe = &vv.x;
                #pragma unroll
                for (int e = 0; e < 4; e++) {
                    int gx = gx0 + e;
                    if ((unsigned)gx < WW)
                        pe[e] = fmaf(A, ip[(size_t)gy * WW + gx], Bc);
                }
            }
        }
        int cb = q4 * 4 - 1;
        if (cb >= 0) BA(r, cb) = vv.x;
        BA(r, cb + 1) = vv.y;
        BA(r, cb + 2) = vv.z;
        BA(r, cb + 3) = vv.w;
    }

    #pragma unroll
    for (int it = 0; it < 3; it++) {
        const int m = 5 * it;
        const int C = 84 - 2 * m;               // 84, 74, 64
        const int R = 94 - 2 * m;
        const int G16 = (C + 15) >> 4;          // 6, 5, 4
        const int lastcol = m + 5 + C - 1;
        __syncthreads();
        // sliding row sums, 16 cols per task; r-fastest (conflict-free LDS)
        for (int i = t; i < R * G16; i += 256) {
            int g = i / R; int r = m + (i - g * R);
            int xg = m + 5 + g * 16;
            if (xg + 15 <= lastcol) {
                // fast path: full strip, window max read xg+20 <= 93-m
                float v[26];
                #pragma unroll
                for (int d = 0; d < 26; d++) v[d] = BA(r, xg - 5 + d);
                float s = v[0];
                #pragma unroll
                for (int d = 1; d < 11; d++) s += v[d];
                BB(r, xg) = s;
                #pragma unroll
                for (int k = 1; k < 16; k++) {
                    s += v[10 + k] - v[k - 1];
                    BB(r, xg + k) = s;
                }
            } else {
                float v[26];
                #pragma unroll
                for (int d = 0; d < 26; d++) {
                    int idx = xg - 5 + d; if (idx > 93) idx = 93;
                    v[d] = BA(r, idx);
                }
                float s = v[0];
                #pragma unroll
                for (int d = 1; d < 11; d++) s += v[d];
                BB(r, xg) = s;
                #pragma unroll
                for (int k = 1; k < 16; k++) {
                    if (xg + k > lastcol) break;
                    s += v[10 + k] - v[k - 1];
                    BB(r, xg + k) = s;
                }
            }
        }
        __syncthreads();
        // sliding col sums + emphase + next-iter affine; x-fastest (conflict-free)
        for (int i = t; i < C * G16; i += 256) {
            int g = i / C; int x = m + 5 + (i - g * C);
            int yg = m + 5 + g * 16;
            int gx = x0 - 15 + x;
            bool gxok = (unsigned)gx < WW;
            if (yg + 15 <= lastcol) {
                float cv[26];
                #pragma unroll
                for (int d = 0; d < 26; d++) cv[d] = BB(yg - 5 + d, x);
                float col = cv[0];
                #pragma unroll
                for (int d = 1; d < 11; d++) col += cv[d];
                #pragma unroll
                for (int k = 0; k < 16; k++) {
                    int y = yg + k;
                    if (k > 0) col += cv[10 + k] - cv[k - 1];
                    int gy = y0 - 15 + y;
                    float o = 0.f;
                    if (gxok && (unsigned)gy < HH) {
                        float s = BA(y, x);
                        float e = fmaf(w, s - col * (1.0f / 121.0f), s);
                        o = (it < 2) ? fmaf(A, e, Bc) : e;
                    }
                    BA(y, x) = o;
                }
            } else {
                float cv[26];
                #pragma unroll
                for (int d = 0; d < 26; d++) {
                    int idx = yg - 5 + d; if (idx > 93) idx = 93;
                    cv[d] = BB(idx, x);
                }
                float col = cv[0];
                #pragma unroll
                for (int d = 1; d < 11; d++) col += cv[d];
                #pragma unroll
                for (int k = 0; k < 16; k++) {
                    int y = yg + k;
                    if (y > lastcol) break;
                    if (k > 0) col += cv[10 + k] - cv[k - 1];
                    int gy = y0 - 15 + y;
                    float o = 0.f;
                    if (gxok && (unsigned)gy < HH) {
                        float s = BA(y, x);
                        float e = fmaf(w, s - col * (1.0f / 121.0f), s);
                        o = (it < 2) ? fmaf(A, e, Bc) : e;
                    }
                    BA(y, x) = o;
                }
            }
        }
    }
    __syncthreads();
    float* op = out + ((size_t)b * C2 + c) * HH * WW;
    for (int i = t; i < 64 * 64; i += 256) {
        int ly = i >> 6, lx = i & 63;
        op[(size_t)(y0 + ly) * WW + (x0 + lx)] = BA(15 + ly, 15 + lx);
    }
    #undef BA
    #undef BB
}

// ---------------------------------------------------------------------------
extern "C" void kernel_launch(void* const* d_in, const int* in_sizes, int n_in,
                              void* d_out, int out_size) {
    const float* x        = (const float*)d_in[0];
    const float* w1       = (const float*)d_in[1];
    const float* b1       = (const float*)d_in[2];
    const float* w2       = (const float*)d_in[3];
    const float* b2       = (const float*)d_in[4];
    const float* down_k   = (const float*)d_in[5];
    const float* down_b   = (const float*)d_in[6];
    const float* ft_gamma = (const float*)d_in[7];
    const float* ft_beta  = (const float*)d_in[8];
    const float* ft_mean  = (const float*)d_in[9];
    const float* ft_var   = (const float*)d_in[10];
    const float* ft_k     = (const float*)d_in[11];
    const float* ft_b     = (const float*)d_in[12];
    const float* emph_w   = (const float*)d_in[13];
    const float* interp_k = (const float*)d_in[14];
    const float* interp_b = (const float*)d_in[15];
    const float* i_gamma  = (const float*)d_in[16];
    const float* i_beta   = (const float*)d_in[17];
    const float* i_mean   = (const float*)d_in[18];
    const float* i_var    = (const float*)d_in[19];
    float* out = (float*)d_out;

    static int ft3_attr_set = 0;
    if (!ft3_attr_set) {
        cudaFuncSetAttribute(k_ft3, cudaFuncAttributeMaxDynamicSharedMemorySize, FT3_SMEM);
        ft3_attr_set = 1;
    }

    k_md1<<<dim3(11, 21, 2), 512>>>(x, w1, b1, w2, b2, down_k, down_b);
    k_pyr<<<BATCH * C2, 256>>>(down_k, down_b);
    k_acc<<<dim3(16, 16, 64), dim3(32, 4)>>>(interp_k, interp_b, i_gamma, i_beta, i_mean, i_var);
    k_ft3<<<dim3(8, 8, 128), 256, FT3_SMEM>>>(
        out, ft_gamma, ft_beta, ft_mean, ft_var, ft_k, ft_b, emph_w);
}